// round 15
// baseline (speedup 1.0000x reference)
#include <cuda_runtime.h>
#include <cuda_fp16.h>
#include <math.h>

#define NN 100000
#define EE 1600000
#define C 64
#define OC 16

// ---------------- scratch (static device globals; no runtime allocation) ----
// INVARIANT: g_deg is all-zero at every kernel_launch entry (zero-init at load,
// k_scanA resets it after consuming). Deterministic: identical work every call.
__device__ int   g_deg[NN];
__device__ float g_dinv[NN];
__device__ int   g_rowptr[NN + 1];
__device__ int   g_fill[NN];
__device__ int   g_bsum[128];
__device__ __align__(256) int     g_srcs[EE];     // CSR column indices (src node)
__device__ __align__(256) __half2 g_t16[NN * 32]; // (X@W)*dinv[row], fp16
__device__ __align__(256) float   g_h[NN * C];    // layer-1 output (post relu), fp32

// Per-block int32/int64 self-detection: for little-endian int64 with values
// < 2^31 every odd 32-bit word is zero; for random int32 in [0,1e5) the odds
// all 32 odd words are zero is ~1e-160.
__device__ __forceinline__ int detect_is64(const int* __restrict__ ei32, int tid) {
    __shared__ int s_is64;
    if (tid < 32) {
        int w = __ldg(&ei32[2 * tid + 1]);
        int all0 = __all_sync(0xffffffffu, w == 0);
        if (tid == 0) s_is64 = all0;
    }
    __syncthreads();
    return s_is64;
}

// ---------------- setup kernels --------------------------------------------
__global__ void k_hist(const int* __restrict__ ei32) {
    int tid = threadIdx.x;
    int is64 = detect_is64(ei32, tid);
    int idx = blockIdx.x * blockDim.x + tid;
    int stride = gridDim.x * blockDim.x;
    if (!is64) {
        const int4* pd = (const int4*)(ei32 + EE);
        for (int e4 = idx; e4 < EE / 4; e4 += stride) {
            int4 d = __ldg(&pd[e4]);
            atomicAdd(&g_deg[d.x], 1); atomicAdd(&g_deg[d.y], 1);
            atomicAdd(&g_deg[d.z], 1); atomicAdd(&g_deg[d.w], 1);
        }
    } else {
        const int4* pd = (const int4*)(ei32 + 2 * EE);   // int64 dst row
        for (int e2 = idx; e2 < EE / 2; e2 += stride) {  // 2 edges per int4
            int4 d = __ldg(&pd[e2]);
            atomicAdd(&g_deg[d.x], 1); atomicAdd(&g_deg[d.z], 1);
        }
    }
}

// block-level scan of deg (1024 elems/block): block-local exclusive prefix ->
// g_rowptr, block total -> g_bsum, computes dinv, resets g_deg to 0.
__global__ void k_scanA() {
    int tid = threadIdx.x;
    int i = blockIdx.x * 1024 + tid;
    int v = 0;
    if (i < NN) {
        v = g_deg[i];
        g_deg[i] = 0;                                  // restore zero-invariant
        g_dinv[i] = rsqrtf((float)(v + 1));            // +1 self loop
    }

    int lane = tid & 31, wid = tid >> 5;
    int incl = v;
#pragma unroll
    for (int o = 1; o < 32; o <<= 1) {
        int t = __shfl_up_sync(0xffffffffu, incl, o);
        if (lane >= o) incl += t;
    }
    __shared__ int wsum[32];
    if (lane == 31) wsum[wid] = incl;
    __syncthreads();
    if (wid == 0) {
        int xi = wsum[lane];
#pragma unroll
        for (int o = 1; o < 32; o <<= 1) {
            int t = __shfl_up_sync(0xffffffffu, xi, o);
            if (lane >= o) xi += t;
        }
        wsum[lane] = xi;
    }
    __syncthreads();
    int base = wid ? wsum[wid - 1] : 0;
    if (i < NN) g_rowptr[i] = base + incl - v;          // block-local exclusive
    if (tid == 1023) g_bsum[blockIdx.x] = base + incl;  // block TOTAL
}

// adds global prefix: each 256-thread block lies in one 1024-group g;
// prefix = sum of g_bsum[0..g-1] via block-local reduction (<=97 values).
__global__ void k_scanC() {
    int tid = threadIdx.x;
    int g = blockIdx.x >> 2;
    int v = (tid < g) ? g_bsum[tid] : 0;      // g <= 97 < 256
#pragma unroll
    for (int o = 16; o >= 1; o >>= 1) v += __shfl_xor_sync(0xffffffffu, v, o);
    __shared__ int wred[8];
    if ((tid & 31) == 0) wred[tid >> 5] = v;
    __syncthreads();
    __shared__ int s_pref;
    if (tid == 0) {
        int p = 0;
#pragma unroll
        for (int w = 0; w < 8; w++) p += wred[w];
        s_pref = p;
    }
    __syncthreads();
    int pref = s_pref;

    int i = blockIdx.x * 256 + tid;
    if (i < NN) {
        int r = g_rowptr[i] + pref;
        g_rowptr[i] = r;
        g_fill[i]   = r;
    }
    if (i == 0) g_rowptr[NN] = EE;
}

// scatter src index into per-dst CSR bucket (4-byte payload, no weights)
__global__ void k_scatter(const int* __restrict__ ei32) {
    int tid = threadIdx.x;
    int is64 = detect_is64(ei32, tid);
    int idx = blockIdx.x * blockDim.x + tid;
    int stride = gridDim.x * blockDim.x;
    if (!is64) {
        const int4* ps = (const int4*)ei32;
        const int4* pd = (const int4*)(ei32 + EE);
        for (int e4 = idx; e4 < EE / 4; e4 += stride) {
            int4 s = __ldg(&ps[e4]);
            int4 d = __ldg(&pd[e4]);
            int sa[4] = {s.x, s.y, s.z, s.w};
            int da[4] = {d.x, d.y, d.z, d.w};
#pragma unroll
            for (int q = 0; q < 4; q++) {
                int pos = atomicAdd(&g_fill[da[q]], 1);
                g_srcs[pos] = sa[q];
            }
        }
    } else {
        const long long* es = (const long long*)ei32;
        for (int e = idx; e < EE; e += stride) {
            int s = (int)__ldg(&es[e]);
            int d = (int)__ldg(&es[EE + e]);
            int pos = atomicAdd(&g_fill[d], 1);
            g_srcs[pos] = s;
        }
    }
}

// ---------------- GEMM: g_t16[i,:] = dinv16[i] * (X[i,:] @ W) (fp16 out) ---
// 128 rows x 64 cols per block, 256 threads, 8x4 register tile per thread.
// X == nullptr means "read g_h" (layer 2 input).
// SCALE=1: multiply rows by g_dinv (requires scanA done). SCALE=0: defer — the
// aggregation pass multiplies the gathered sum by dinv[src]? NO — scaling must
// be per-src; layer-1 GEMM runs concurrently with the scan, so it CANNOT read
// g_dinv. Instead it stores raw t16 and k_agg applies dinv[src] per gather.
template <int SCALE>
__global__ __launch_bounds__(256) void k_gemm64(const float* __restrict__ X,
                                                const float* __restrict__ W) {
    __shared__ float xs[128][65];
    __shared__ float ws[64][64];
    int tid = threadIdx.x;
    int row0 = blockIdx.x * 128;
    const float* Xp = X ? X : g_h;

    const float4* W4 = (const float4*)W;
    float4* ws4 = (float4*)&ws[0][0];
#pragma unroll
    for (int q = 0; q < 4; q++) ws4[tid + q * 256] = __ldg(&W4[tid + q * 256]);

#pragma unroll
    for (int q = 0; q < 8; q++) {
        int j = tid + q * 256;              // 0..2047
        int r = j >> 4, k4 = j & 15;
        int gr = row0 + r;
        float4 v = (gr < NN) ? __ldg(&((const float4*)Xp)[gr * 16 + k4])
                             : make_float4(0.f, 0.f, 0.f, 0.f);
        xs[r][k4 * 4 + 0] = v.x; xs[r][k4 * 4 + 1] = v.y;
        xs[r][k4 * 4 + 2] = v.z; xs[r][k4 * 4 + 3] = v.w;
    }
    __syncthreads();

    int tx = tid & 15, ty = tid >> 4;
    float acc[8][4];
#pragma unroll
    for (int i = 0; i < 8; i++)
#pragma unroll
        for (int j = 0; j < 4; j++) acc[i][j] = 0.f;

#pragma unroll 8
    for (int k = 0; k < 64; k++) {
        float a[8];
#pragma unroll
        for (int i = 0; i < 8; i++) a[i] = xs[ty * 8 + i][k];
        float4 b = *(const float4*)&ws[k][tx * 4];
#pragma unroll
        for (int i = 0; i < 8; i++) {
            acc[i][0] = fmaf(a[i], b.x, acc[i][0]);
            acc[i][1] = fmaf(a[i], b.y, acc[i][1]);
            acc[i][2] = fmaf(a[i], b.z, acc[i][2]);
            acc[i][3] = fmaf(a[i], b.w, acc[i][3]);
        }
    }

#pragma unroll
    for (int i = 0; i < 8; i++) {
        int gr = row0 + ty * 8 + i;
        if (gr < NN) {
            float dv = SCALE ? __ldg(&g_dinv[gr]) : 1.0f;
            union { __half2 h[2]; uint2 u; } pk;
            pk.h[0] = __floats2half2_rn(acc[i][0] * dv, acc[i][1] * dv);
            pk.h[1] = __floats2half2_rn(acc[i][2] * dv, acc[i][3] * dv);
            ((uint2*)g_t16)[gr * 16 + tx] = pk.u;
        }
    }
}

// ---------------- aggregation: warp per node, CSR gather-reduce ------------
// PRESCALED=1: t16 rows already carry dinv[src]  -> sum directly.
// PRESCALED=0: apply dinv[src] at gather time (layer 1, overlapped GEMM).
// out[n] = relu( dinv[n] * (dinv[n]*t[n]... ) )  -- self term uses dinv[n].
// FC=0: -> g_h.  FC=1: fused FC(64->16) + log_softmax -> out.
template <int PRESCALED, int FC>
__global__ void k_agg(const float* __restrict__ bias,
                      const float* __restrict__ Wfc,
                      const float* __restrict__ bfc,
                      float* __restrict__ out) {
    int n    = (blockIdx.x * blockDim.x + threadIdx.x) >> 5;
    int lane = threadIdx.x & 31;
    if (n >= NN) return;
    const __half2* T16 = (const __half2*)g_t16;

    float dn = __ldg(&g_dinv[n]);
    float2 sv = __half22float2(__ldg(&T16[n * 32 + lane]));
    float selfw = PRESCALED ? 1.0f : dn;        // self term weight on raw t
    float a0 = sv.x * selfw, a1 = sv.y * selfw;

    int j = g_rowptr[n], end = g_rowptr[n + 1];
    for (; j + 16 <= end; j += 16) {
        int src[16];
#pragma unroll
        for (int q = 0; q < 16; q++) src[q] = __ldg(&g_srcs[j + q]);
        float2 v[16];
#pragma unroll
        for (int q = 0; q < 16; q++)
            v[q] = __half22float2(__ldg(&T16[src[q] * 32 + lane]));
        if (PRESCALED) {
#pragma unroll
            for (int q = 0; q < 16; q++) { a0 += v[q].x; a1 += v[q].y; }
        } else {
            float dv[16];
#pragma unroll
            for (int q = 0; q < 16; q++) dv[q] = __ldg(&g_dinv[src[q]]);
#pragma unroll
            for (int q = 0; q < 16; q++) {
                a0 = fmaf(v[q].x, dv[q], a0);
                a1 = fmaf(v[q].y, dv[q], a1);
            }
        }
    }
    for (; j < end; j++) {
        int src = __ldg(&g_srcs[j]);
        float2 v = __half22float2(__ldg(&T16[src * 32 + lane]));
        float dv = PRESCALED ? 1.0f : __ldg(&g_dinv[src]);
        a0 = fmaf(v.x, dv, a0); a1 = fmaf(v.y, dv, a1);
    }

    float2 b = __ldg(&((const float2*)bias)[lane]);
    a0 = fmaxf(fmaf(a0, dn, b.x), 0.f);
    a1 = fmaxf(fmaf(a1, dn, b.y), 0.f);

    if (FC == 0) {
        ((float2*)g_h)[n * 32 + lane] = make_float2(a0, a1);
    } else {
        // fused FC: channels (2*lane, 2*lane+1) x Wfc[64][16]
        const float4* W4 = (const float4*)Wfc;
        float p[16];
#pragma unroll
        for (int q = 0; q < 4; q++) {
            float4 w0 = __ldg(&W4[(2 * lane) * 4 + q]);
            float4 w1 = __ldg(&W4[(2 * lane + 1) * 4 + q]);
            p[4 * q + 0] = a0 * w0.x + a1 * w1.x;
            p[4 * q + 1] = a0 * w0.y + a1 * w1.y;
            p[4 * q + 2] = a0 * w0.z + a1 * w1.z;
            p[4 * q + 3] = a0 * w0.w + a1 * w1.w;
        }
#pragma unroll
        for (int off = 16; off >= 1; off >>= 1)
#pragma unroll
            for (int c = 0; c < 16; c++)
                p[c] += __shfl_xor_sync(0xffffffffu, p[c], off);

        float m = -3.4e38f;
#pragma unroll
        for (int c = 0; c < 16; c++) { p[c] += __ldg(&bfc[c]); m = fmaxf(m, p[c]); }

        float val = 0.f;
#pragma unroll
        for (int c = 0; c < 16; c++) if (lane == c) val = p[c];
        float ex = (lane < 16) ? expf(val - m) : 0.f;
#pragma unroll
        for (int off = 8; off >= 1; off >>= 1)
            ex += __shfl_xor_sync(0xffffffffu, ex, off);
        float lse = m + logf(ex);

        if (lane < 16) out[n * 16 + lane] = val - lse;
    }
}

// ---------------- launch ----------------------------------------------------
// Layer-1 GEMM is graph-independent: forked onto a side stream so it overlaps
// the hist/scan/scatter chain (disjoint pipes: FMA vs L2-atomics). Standard
// event fork/join — capture-legal, produces a branched graph.
extern "C" void kernel_launch(void* const* d_in, const int* in_sizes, int n_in,
                              void* d_out, int out_size) {
    const float* x    = (const float*)d_in[0];
    const int*   ei32 = (const int*)d_in[1];   // int32 or int64 — detected on device
    const float* W1   = (const float*)d_in[2];
    const float* b1   = (const float*)d_in[3];
    const float* W2   = (const float*)d_in[4];
    const float* b2   = (const float*)d_in[5];
    const float* Wfc  = (const float*)d_in[6];
    const float* bfc  = (const float*)d_in[7];
    float*       out  = (float*)d_out;

    static cudaStream_t s2 = nullptr;
    static cudaEvent_t ev_fork = nullptr, ev_join = nullptr;
    if (!s2) {
        cudaStreamCreateWithFlags(&s2, cudaStreamNonBlocking);
        cudaEventCreateWithFlags(&ev_fork, cudaEventDisableTiming);
        cudaEventCreateWithFlags(&ev_join, cudaEventDisableTiming);
    }

    // fork: layer-1 GEMM (raw, unscaled — g_dinv not ready yet) on s2
    cudaEventRecord(ev_fork, 0);
    cudaStreamWaitEvent(s2, ev_fork, 0);
    k_gemm64<0><<<(NN + 127) / 128, 256, 0, s2>>>(x, W1);
    cudaEventRecord(ev_join, s2);

    // main stream: graph build chain
    k_hist<<<1024, 256>>>(ei32);
    k_scanA<<<(NN + 1023) / 1024, 1024>>>();
    k_scanC<<<(NN + 255) / 256, 256>>>();
    k_scatter<<<1024, 256>>>(ei32);

    // join, then aggregate (applies dinv[src] at gather time for layer 1)
    cudaStreamWaitEvent(0, ev_join, 0);
    k_agg<0, 0><<<(NN + 7) / 8, 256>>>(b1, nullptr, nullptr, nullptr);
    k_gemm64<1><<<(NN + 127) / 128, 256>>>(nullptr, W2);
    k_agg<1, 1><<<(NN + 7) / 8, 256>>>(b2, Wfc, bfc, out);
}

// round 16
// speedup vs baseline: 1.1623x; 1.1623x over previous
#include <cuda_runtime.h>
#include <cuda_fp16.h>
#include <mma.h>
#include <math.h>

#define NN 100000
#define EE 1600000
#define C 64
#define OC 16

using namespace nvcuda;

// ---------------- scratch (static device globals; no runtime allocation) ----
// INVARIANT: g_deg is all-zero at every kernel_launch entry (zero-init at load,
// k_scanA resets it after consuming). Deterministic: identical work every call.
__device__ int   g_deg[NN];
__device__ float g_dinv[NN];
__device__ int   g_rowptr[NN + 1];
__device__ int   g_fill[NN];
__device__ int   g_bsum[128];
__device__ __align__(256) int     g_srcs[EE];     // CSR column indices (src node)
__device__ __align__(256) __half2 g_t16[NN * 32]; // (X@W)*dinv[row], fp16
__device__ __align__(256) __half2 g_h16[NN * 32]; // layer-1 output (post relu), fp16

// Per-block int32/int64 self-detection: for little-endian int64 with values
// < 2^31 every odd 32-bit word is zero; for random int32 in [0,1e5) the odds
// all 32 odd words are zero is ~1e-160.
__device__ __forceinline__ int detect_is64(const int* __restrict__ ei32, int tid) {
    __shared__ int s_is64;
    if (tid < 32) {
        int w = __ldg(&ei32[2 * tid + 1]);
        int all0 = __all_sync(0xffffffffu, w == 0);
        if (tid == 0) s_is64 = all0;
    }
    __syncthreads();
    return s_is64;
}

// ---------------- setup kernels --------------------------------------------
__global__ void k_hist(const int* __restrict__ ei32) {
    int tid = threadIdx.x;
    int is64 = detect_is64(ei32, tid);
    int idx = blockIdx.x * blockDim.x + tid;
    int stride = gridDim.x * blockDim.x;
    if (!is64) {
        const int4* pd = (const int4*)(ei32 + EE);
        for (int e4 = idx; e4 < EE / 4; e4 += stride) {
            int4 d = __ldg(&pd[e4]);
            atomicAdd(&g_deg[d.x], 1); atomicAdd(&g_deg[d.y], 1);
            atomicAdd(&g_deg[d.z], 1); atomicAdd(&g_deg[d.w], 1);
        }
    } else {
        const int4* pd = (const int4*)(ei32 + 2 * EE);   // int64 dst row
        for (int e2 = idx; e2 < EE / 2; e2 += stride) {  // 2 edges per int4
            int4 d = __ldg(&pd[e2]);
            atomicAdd(&g_deg[d.x], 1); atomicAdd(&g_deg[d.z], 1);
        }
    }
}

// block-level scan of deg (1024 elems/block): block-local exclusive prefix ->
// g_rowptr, block total -> g_bsum, computes dinv, resets g_deg to 0.
__global__ void k_scanA() {
    int tid = threadIdx.x;
    int i = blockIdx.x * 1024 + tid;
    int v = 0;
    if (i < NN) {
        v = g_deg[i];
        g_deg[i] = 0;                                  // restore zero-invariant
        g_dinv[i] = rsqrtf((float)(v + 1));            // +1 self loop
    }

    int lane = tid & 31, wid = tid >> 5;
    int incl = v;
#pragma unroll
    for (int o = 1; o < 32; o <<= 1) {
        int t = __shfl_up_sync(0xffffffffu, incl, o);
        if (lane >= o) incl += t;
    }
    __shared__ int wsum[32];
    if (lane == 31) wsum[wid] = incl;
    __syncthreads();
    if (wid == 0) {
        int xi = wsum[lane];
#pragma unroll
        for (int o = 1; o < 32; o <<= 1) {
            int t = __shfl_up_sync(0xffffffffu, xi, o);
            if (lane >= o) xi += t;
        }
        wsum[lane] = xi;
    }
    __syncthreads();
    int base = wid ? wsum[wid - 1] : 0;
    if (i < NN) g_rowptr[i] = base + incl - v;          // block-local exclusive
    if (tid == 1023) g_bsum[blockIdx.x] = base + incl;  // block TOTAL
}

// adds global prefix: each 256-thread block lies in one 1024-group g;
// prefix = sum of g_bsum[0..g-1] via block-local reduction (<=97 values).
__global__ void k_scanC() {
    int tid = threadIdx.x;
    int g = blockIdx.x >> 2;
    int v = (tid < g) ? g_bsum[tid] : 0;      // g <= 97 < 256
#pragma unroll
    for (int o = 16; o >= 1; o >>= 1) v += __shfl_xor_sync(0xffffffffu, v, o);
    __shared__ int wred[8];
    if ((tid & 31) == 0) wred[tid >> 5] = v;
    __syncthreads();
    __shared__ int s_pref;
    if (tid == 0) {
        int p = 0;
#pragma unroll
        for (int w = 0; w < 8; w++) p += wred[w];
        s_pref = p;
    }
    __syncthreads();
    int pref = s_pref;

    int i = blockIdx.x * 256 + tid;
    if (i < NN) {
        int r = g_rowptr[i] + pref;
        g_rowptr[i] = r;
        g_fill[i]   = r;
    }
    if (i == 0) g_rowptr[NN] = EE;
}

// scatter src index into per-dst CSR bucket (4-byte payload, no weights)
__global__ void k_scatter(const int* __restrict__ ei32) {
    int tid = threadIdx.x;
    int is64 = detect_is64(ei32, tid);
    int idx = blockIdx.x * blockDim.x + tid;
    int stride = gridDim.x * blockDim.x;
    if (!is64) {
        const int4* ps = (const int4*)ei32;
        const int4* pd = (const int4*)(ei32 + EE);
        for (int e4 = idx; e4 < EE / 4; e4 += stride) {
            int4 s = __ldg(&ps[e4]);
            int4 d = __ldg(&pd[e4]);
            int sa[4] = {s.x, s.y, s.z, s.w};
            int da[4] = {d.x, d.y, d.z, d.w};
#pragma unroll
            for (int q = 0; q < 4; q++) {
                int pos = atomicAdd(&g_fill[da[q]], 1);
                g_srcs[pos] = sa[q];
            }
        }
    } else {
        const long long* es = (const long long*)ei32;
        for (int e = idx; e < EE; e += stride) {
            int s = (int)__ldg(&es[e]);
            int d = (int)__ldg(&es[EE + e]);
            int pos = atomicAdd(&g_fill[d], 1);
            g_srcs[pos] = s;
        }
    }
}

// ---------------- tensor-core GEMM: g_t16[i,:] = dinv[i]*(X[i,:] @ W) ------
// 128 rows x 64 cols per block, 256 threads (8 warps). wmma m16n16k16,
// fp16 operands, fp32 accumulate. Warp w owns row-tile w (16 rows), loops
// over 4 col-tiles. INHALF=1: input is g_h16 (fp16). INHALF=0: fp32 X.
template <int INHALF>
__global__ __launch_bounds__(256) void k_gemm_tc(const float* __restrict__ X,
                                                 const float* __restrict__ W) {
    __shared__ __half xs[128][72];   // lda=72 halves (8-byte aligned rows)
    __shared__ __half ws[64][72];
    __shared__ float  os[128][68];   // epilogue staging
    int tid = threadIdx.x;
    int row0 = blockIdx.x * 128;

    // W [64][64] fp32 -> fp16 smem
    const float4* W4 = (const float4*)W;
#pragma unroll
    for (int q = 0; q < 4; q++) {
        int j = tid + q * 256;            // 1024 float4 groups
        int r = j >> 4, c4 = j & 15;
        float4 v = __ldg(&W4[j]);
        union { __half2 h[2]; uint2 u; } pk;
        pk.h[0] = __floats2half2_rn(v.x, v.y);
        pk.h[1] = __floats2half2_rn(v.z, v.w);
        *(uint2*)&ws[r][c4 * 4] = pk.u;
    }

    // X tile [128][64] -> fp16 smem
#pragma unroll
    for (int q = 0; q < 8; q++) {
        int j = tid + q * 256;            // 2048 groups of 4 elements
        int r = j >> 4, k4 = j & 15;
        int gr = row0 + r;
        uint2 u;
        if (INHALF) {
            u = (gr < NN) ? __ldg(&((const uint2*)g_h16)[gr * 16 + k4])
                          : make_uint2(0u, 0u);
        } else {
            float4 v = (gr < NN) ? __ldg(&((const float4*)X)[gr * 16 + k4])
                                 : make_float4(0.f, 0.f, 0.f, 0.f);
            union { __half2 h[2]; uint2 uu; } pk;
            pk.h[0] = __floats2half2_rn(v.x, v.y);
            pk.h[1] = __floats2half2_rn(v.z, v.w);
            u = pk.uu;
        }
        *(uint2*)&xs[r][k4 * 4] = u;
    }
    __syncthreads();

    // wmma: warp w -> rows [w*16, w*16+16), 4 col tiles
    int w = tid >> 5;
    wmma::fragment<wmma::accumulator, 16, 16, 16, float> fc[4];
#pragma unroll
    for (int ct = 0; ct < 4; ct++) wmma::fill_fragment(fc[ct], 0.0f);
#pragma unroll
    for (int k = 0; k < 4; k++) {
        wmma::fragment<wmma::matrix_a, 16, 16, 16, __half, wmma::row_major> fa;
        wmma::load_matrix_sync(fa, &xs[w * 16][k * 16], 72);
#pragma unroll
        for (int ct = 0; ct < 4; ct++) {
            wmma::fragment<wmma::matrix_b, 16, 16, 16, __half, wmma::row_major> fb;
            wmma::load_matrix_sync(fb, &ws[k * 16][ct * 16], 72);
            wmma::mma_sync(fc[ct], fa, fb, fc[ct]);
        }
    }
#pragma unroll
    for (int ct = 0; ct < 4; ct++)
        wmma::store_matrix_sync(&os[w * 16][ct * 16], fc[ct], 68, wmma::mem_row_major);
    __syncthreads();

    // epilogue: scale by dinv[row], pack fp16, store (4 cols per thread-group)
    int tx = tid & 15, ty = tid >> 4;
#pragma unroll
    for (int i = 0; i < 8; i++) {
        int r = ty * 8 + i;
        int gr = row0 + r;
        if (gr < NN) {
            float dv = __ldg(&g_dinv[gr]);
            float4 v = *(const float4*)&os[r][tx * 4];
            union { __half2 h[2]; uint2 u; } pk;
            pk.h[0] = __floats2half2_rn(v.x * dv, v.y * dv);
            pk.h[1] = __floats2half2_rn(v.z * dv, v.w * dv);
            ((uint2*)g_t16)[gr * 16 + tx] = pk.u;
        }
    }
}

// ---------------- aggregation: warp per node, CSR gather-reduce ------------
// out[n] = relu( dinv[n] * (t16[n] + sum_{src} t16[src]) + bias )
// FC=0: -> g_h16 (fp16).  FC=1: fused FC(64->16) + log_softmax -> out.
template <int FC>
__global__ void k_agg(const float* __restrict__ bias,
                      const float* __restrict__ Wfc,
                      const float* __restrict__ bfc,
                      float* __restrict__ out) {
    int n    = (blockIdx.x * blockDim.x + threadIdx.x) >> 5;
    int lane = threadIdx.x & 31;
    if (n >= NN) return;
    const __half2* T16 = (const __half2*)g_t16;

    float2 sv = __half22float2(__ldg(&T16[n * 32 + lane]));
    float a0 = sv.x, a1 = sv.y;                 // self term (t16 already * dinv)

    int j = g_rowptr[n], end = g_rowptr[n + 1];
    for (; j + 16 <= end; j += 16) {
        int src[16];
#pragma unroll
        for (int q = 0; q < 16; q++) src[q] = __ldg(&g_srcs[j + q]);
        float2 v[16];
#pragma unroll
        for (int q = 0; q < 16; q++)
            v[q] = __half22float2(__ldg(&T16[src[q] * 32 + lane]));
#pragma unroll
        for (int q = 0; q < 16; q++) { a0 += v[q].x; a1 += v[q].y; }
    }
    for (; j + 4 <= end; j += 4) {
        int src[4];
#pragma unroll
        for (int q = 0; q < 4; q++) src[q] = __ldg(&g_srcs[j + q]);
        float2 v[4];
#pragma unroll
        for (int q = 0; q < 4; q++)
            v[q] = __half22float2(__ldg(&T16[src[q] * 32 + lane]));
#pragma unroll
        for (int q = 0; q < 4; q++) { a0 += v[q].x; a1 += v[q].y; }
    }
    for (; j < end; j++) {
        float2 v = __half22float2(__ldg(&T16[__ldg(&g_srcs[j]) * 32 + lane]));
        a0 += v.x; a1 += v.y;
    }

    float dn = __ldg(&g_dinv[n]);
    float2 b = __ldg(&((const float2*)bias)[lane]);
    a0 = fmaxf(fmaf(a0, dn, b.x), 0.f);
    a1 = fmaxf(fmaf(a1, dn, b.y), 0.f);

    if (FC == 0) {
        g_h16[n * 32 + lane] = __floats2half2_rn(a0, a1);
    } else {
        // fused FC: channels (2*lane, 2*lane+1) x Wfc[64][16]
        const float4* W4 = (const float4*)Wfc;
        float p[16];
#pragma unroll
        for (int q = 0; q < 4; q++) {
            float4 w0 = __ldg(&W4[(2 * lane) * 4 + q]);
            float4 w1 = __ldg(&W4[(2 * lane + 1) * 4 + q]);
            p[4 * q + 0] = a0 * w0.x + a1 * w1.x;
            p[4 * q + 1] = a0 * w0.y + a1 * w1.y;
            p[4 * q + 2] = a0 * w0.z + a1 * w1.z;
            p[4 * q + 3] = a0 * w0.w + a1 * w1.w;
        }
#pragma unroll
        for (int off = 16; off >= 1; off >>= 1)
#pragma unroll
            for (int c = 0; c < 16; c++)
                p[c] += __shfl_xor_sync(0xffffffffu, p[c], off);

        float m = -3.4e38f;
#pragma unroll
        for (int c = 0; c < 16; c++) { p[c] += __ldg(&bfc[c]); m = fmaxf(m, p[c]); }

        float val = 0.f;
#pragma unroll
        for (int c = 0; c < 16; c++) if (lane == c) val = p[c];
        float ex = (lane < 16) ? expf(val - m) : 0.f;
#pragma unroll
        for (int off = 8; off >= 1; off >>= 1)
            ex += __shfl_xor_sync(0xffffffffu, ex, off);
        float lse = m + logf(ex);

        if (lane < 16) out[n * 16 + lane] = val - lse;
    }
}

// ---------------- launch ----------------------------------------------------
extern "C" void kernel_launch(void* const* d_in, const int* in_sizes, int n_in,
                              void* d_out, int out_size) {
    const float* x    = (const float*)d_in[0];
    const int*   ei32 = (const int*)d_in[1];   // int32 or int64 — detected on device
    const float* W1   = (const float*)d_in[2];
    const float* b1   = (const float*)d_in[3];
    const float* W2   = (const float*)d_in[4];
    const float* b2   = (const float*)d_in[5];
    const float* Wfc  = (const float*)d_in[6];
    const float* bfc  = (const float*)d_in[7];
    float*       out  = (float*)d_out;

    k_hist<<<1024, 256>>>(ei32);
    k_scanA<<<(NN + 1023) / 1024, 1024>>>();
    k_scanC<<<(NN + 255) / 256, 256>>>();
    k_scatter<<<1024, 256>>>(ei32);

    k_gemm_tc<0><<<(NN + 127) / 128, 256>>>(x, W1);
    k_agg<0><<<(NN + 7) / 8, 256>>>(b1, nullptr, nullptr, nullptr);
    k_gemm_tc<1><<<(NN + 127) / 128, 256>>>(nullptr, W2);
    k_agg<1><<<(NN + 7) / 8, 256>>>(b2, Wfc, bfc, out);
}